// round 9
// baseline (speedup 1.0000x reference)
#include <cuda_runtime.h>

#define G     8
#define CIN   64
#define COUT  64
#define KS    7
#define PAD   3
#define H     56
#define W     56
#define B     4

#define TH    8
#define TRW   (TH + KS - 1)
#define SP    66

typedef unsigned long long ull;
typedef unsigned int uint;

__device__ float g_q[B*COUT*H*W];
__device__ float g_k[B*COUT*H*W];
__device__ float g_v[B*COUT*H*W];

#define EX2F(dst, src) asm("ex2.approx.ftz.f32 %0, %1;" : "=f"(dst) : "f"(src))

__device__ __forceinline__ ull pk(float lo, float hi) {
    ull r; asm("mov.b64 %0, {%1, %2};" : "=l"(r) : "f"(lo), "f"(hi)); return r;
}
__device__ __forceinline__ void upk(float& lo, float& hi, ull p) {
    asm("mov.b64 {%0, %1}, %2;" : "=f"(lo), "=f"(hi) : "l"(p));
}
__device__ __forceinline__ ull fma2(ull a, ull b, ull c) {
    ull r; asm("fma.rn.f32x2 %0, %1, %2, %3;" : "=l"(r) : "l"(a), "l"(b), "l"(c)); return r;
}
__device__ __forceinline__ ull add2(ull a, ull b) {
    ull r; asm("add.rn.f32x2 %0, %1, %2;" : "=l"(r) : "l"(a), "l"(b)); return r;
}

#define MAGIC2  0x4B4000004B400000ULL
#define NMAGIC2 0xCB400000CB400000ULL
#define NONE2   0xBF800000BF800000ULL
#define ONE2    0x3F8000003F800000ULL
#define C1_2 0x3F3172183F317218ULL
#define C2_2 0x3E75FDF03E75FDF0ULL
#define C3_2 0x3D6433DD3D6433DDULL
#define C4_2 0x3C1E9E723C1E9E72ULL

// packed pair of exp2 taps on FMA/ALU pipes only (no MUFU)
__device__ __forceinline__ void tap2_poly(ull q2, ull k2, ull a2, float v0, float v1,
                                          float& sa, float& oa, float& sb, float& ob) {
    ull l2 = fma2(q2, k2, a2);
    ull t2 = add2(l2, MAGIC2);
    ull u2 = add2(t2, NMAGIC2);     // rint(l)
    ull f2 = fma2(u2, NONE2, l2);   // frac in [-0.5, 0.5]
    ull p  = fma2(f2, C4_2, C3_2);
    p = fma2(f2, p, C2_2);
    p = fma2(f2, p, C1_2);
    p = fma2(f2, p, ONE2);
    float pl, ph, tl, th;
    upk(pl, ph, p); upk(tl, th, t2);
    float e0 = __uint_as_float(__float_as_uint(pl) + __float_as_uint(tl) * 8388608u);
    float e1 = __uint_as_float(__float_as_uint(ph) + __float_as_uint(th) * 8388608u);
    sa += e0; oa = fmaf(e0, v0, oa);
    sb += e1; ob = fmaf(e1, v1, ob);
}

__global__ __launch_bounds__(256)
void qkv_kernel(const float* __restrict__ x,
                const float* __restrict__ wq,
                const float* __restrict__ wk,
                const float* __restrict__ bk,
                const float* __restrict__ wv,
                const float* __restrict__ bv) {
    const float LOG2E = 1.4426950408889634f;
    int idx = blockIdx.x * 256 + threadIdx.x;          // 100,352 threads
    int t = idx / 14;
    int j = idx - t*14;
    int h = t % 56;  t /= 56;
    int dp = t % 4;  t /= 4;
    int g = t % 8;
    int b = t / 8;
    int c0 = g*8 + dp;
    int c1 = c0 + 4;

    const float4* xp = (const float4*)x + ((b*CIN + g*8)*H + h)*14 + j;

    float kb0 = __ldg(&bk[c0]), kb1 = __ldg(&bk[c1]);
    float vb0 = __ldg(&bv[c0]), vb1 = __ldg(&bv[c1]);
    float4 aq0 = make_float4(0.f,0.f,0.f,0.f), aq1 = aq0;
    float4 ak0 = make_float4(kb0,kb0,kb0,kb0), ak1 = make_float4(kb1,kb1,kb1,kb1);
    float4 av0 = make_float4(vb0,vb0,vb0,vb0), av1 = make_float4(vb1,vb1,vb1,vb1);

    #pragma unroll
    for (int i = 0; i < 8; i++) {
        float4 xv = __ldg(xp + i*784);
        float w_q0 = __ldg(&wq[c0*8 + i]) * LOG2E;
        float w_k0 = __ldg(&wk[c0*8 + i]);
        float w_v0 = __ldg(&wv[c0*8 + i]);
        float w_q1 = __ldg(&wq[c1*8 + i]) * LOG2E;
        float w_k1 = __ldg(&wk[c1*8 + i]);
        float w_v1 = __ldg(&wv[c1*8 + i]);
        aq0.x = fmaf(w_q0, xv.x, aq0.x); aq0.y = fmaf(w_q0, xv.y, aq0.y);
        aq0.z = fmaf(w_q0, xv.z, aq0.z); aq0.w = fmaf(w_q0, xv.w, aq0.w);
        ak0.x = fmaf(w_k0, xv.x, ak0.x); ak0.y = fmaf(w_k0, xv.y, ak0.y);
        ak0.z = fmaf(w_k0, xv.z, ak0.z); ak0.w = fmaf(w_k0, xv.w, ak0.w);
        av0.x = fmaf(w_v0, xv.x, av0.x); av0.y = fmaf(w_v0, xv.y, av0.y);
        av0.z = fmaf(w_v0, xv.z, av0.z); av0.w = fmaf(w_v0, xv.w, av0.w);
        aq1.x = fmaf(w_q1, xv.x, aq1.x); aq1.y = fmaf(w_q1, xv.y, aq1.y);
        aq1.z = fmaf(w_q1, xv.z, aq1.z); aq1.w = fmaf(w_q1, xv.w, aq1.w);
        ak1.x = fmaf(w_k1, xv.x, ak1.x); ak1.y = fmaf(w_k1, xv.y, ak1.y);
        ak1.z = fmaf(w_k1, xv.z, ak1.z); ak1.w = fmaf(w_k1, xv.w, ak1.w);
        av1.x = fmaf(w_v1, xv.x, av1.x); av1.y = fmaf(w_v1, xv.y, av1.y);
        av1.z = fmaf(w_v1, xv.z, av1.z); av1.w = fmaf(w_v1, xv.w, av1.w);
    }
    int o0 = ((b*COUT + c0)*H + h)*14 + j;
    int o1 = ((b*COUT + c1)*H + h)*14 + j;
    ((float4*)g_q)[o0] = aq0; ((float4*)g_q)[o1] = aq1;
    ((float4*)g_k)[o0] = ak0; ((float4*)g_k)[o1] = ak1;
    ((float4*)g_v)[o0] = av0; ((float4*)g_v)[o1] = av1;
}

__global__ __launch_bounds__(224, 6)
void attn_kernel(const float* __restrict__ rel_x,
                 const float* __restrict__ rel_y,
                 const float* __restrict__ bk,
                 const float* __restrict__ bv,
                 float* __restrict__ out) {
    __shared__ __align__(16) float ks_[TRW*SP];
    __shared__ __align__(16) float vs_[TRW*SP];

    int ht = blockIdx.x;
    int c  = blockIdx.y;
    int b  = blockIdx.z;
    int h0 = ht * TH;
    int tid = threadIdx.x;
    int d = c & 7;

    int r  = tid / 28;
    int wp = tid - r*28;
    int h  = h0 + r;
    int w0 = wp * 2;
    int cbase = (b*COUT + c)*H;

    float2 qv = ((const float2*)g_q)[(cbase + h)*28 + wp];
    float relv[7];
    #pragma unroll
    for (int jj = 0; jj < 7; jj++)
        relv[jj] = (d < 4) ? __ldg(&rel_x[d*KS + jj]) : __ldg(&rel_y[(d-4)*KS + jj]);
    float kb = __ldg(&bk[c]);
    float vb = __ldg(&bv[c]);

    for (int i = tid; i < TRW*64; i += 224) {
        int pr = i >> 6, pc = i & 63;
        int hy = h0 + pr - PAD, wx = pc - PAD;
        bool in = ((unsigned)hy < (unsigned)H) && ((unsigned)wx < (unsigned)W);
        int gi = (cbase + hy)*W + wx;
        int si = pr*SP + pc;
        ks_[si] = in ? g_k[gi] : kb;
        vs_[si] = in ? g_v[gi] : vb;
    }
    __syncthreads();

    float q0 = qv.x, q1 = qv.y;
    ull q02 = pk(q0, q0), q12 = pk(q1, q1);

    float s0a = 0.f, s0b = 0.f, s1a = 0.f, s1b = 0.f;
    float o0a = 0.f, o0b = 0.f, o1a = 0.f, o1b = 0.f;

    if (d < 4) {
        #pragma unroll
        for (int jy = 0; jy < KS; jy++) {
            const float2* kp = (const float2*)(ks_ + (r + jy)*SP + w0);
            const float2* vp = (const float2*)(vs_ + (r + jy)*SP + w0);
            float2 ka = kp[0], kc = kp[1], ke = kp[2], kg = kp[3];
            float2 va = vp[0], vc = vp[1], ve = vp[2], vg = vp[3];
            float a0 = q0 * relv[jy];
            float a1 = q1 * relv[jy];
            if (jy < 2) {
                ull A0 = pk(a0, a0), A1 = pk(a1, a1);
                tap2_poly(q02, pk(ka.x,ka.y), A0, va.x, va.y, s0a,o0a,s0b,o0b);
                tap2_poly(q02, pk(kc.x,kc.y), A0, vc.x, vc.y, s0a,o0a,s0b,o0b);
                tap2_poly(q02, pk(ke.x,ke.y), A0, ve.x, ve.y, s0a,o0a,s0b,o0b);
                tap2_poly(q12, pk(ka.y,kc.x), A1, va.y, vc.x, s1a,o1a,s1b,o1b);
                tap2_poly(q12, pk(kc.y,ke.x), A1, vc.y, ve.x, s1a,o1a,s1b,o1b);
                tap2_poly(q12, pk(ke.y,kg.x), A1, ve.y, vg.x, s1a,o1a,s1b,o1b);
                float e;
                EX2F(e, fmaf(q0, kg.x, a0)); s0a += e; o0a = fmaf(e, vg.x, o0a);
                EX2F(e, fmaf(q1, kg.y, a1)); s1a += e; o1a = fmaf(e, vg.y, o1a);
            } else {
                float e;
                EX2F(e, fmaf(q0, ka.x, a0)); s0a += e; o0a = fmaf(e, va.x, o0a);
                EX2F(e, fmaf(q0, ka.y, a0)); s0b += e; o0b = fmaf(e, va.y, o0b);
                EX2F(e, fmaf(q0, kc.x, a0)); s0a += e; o0a = fmaf(e, vc.x, o0a);
                EX2F(e, fmaf(q0, kc.y, a0)); s0b += e; o0b = fmaf(e, vc.y, o0b);
                EX2F(e, fmaf(q0, ke.x, a0)); s0a += e; o0a = fmaf(e, ve.x, o0a);
                EX2F(e, fmaf(q0, ke.y, a0)); s0b += e; o0b = fmaf(e, ve.y, o0b);
                EX2F(e, fmaf(q0, kg.x, a0)); s0a += e; o0a = fmaf(e, vg.x, o0a);
                EX2F(e, fmaf(q1, ka.y, a1)); s1a += e; o1a = fmaf(e, va.y, o1a);
                EX2F(e, fmaf(q1, kc.x, a1)); s1b += e; o1b = fmaf(e, vc.x, o1b);
                EX2F(e, fmaf(q1, kc.y, a1)); s1a += e; o1a = fmaf(e, vc.y, o1a);
                EX2F(e, fmaf(q1, ke.x, a1)); s1b += e; o1b = fmaf(e, ve.x, o1b);
                EX2F(e, fmaf(q1, ke.y, a1)); s1a += e; o1a = fmaf(e, ve.y, o1a);
                EX2F(e, fmaf(q1, kg.x, a1)); s1b += e; o1b = fmaf(e, vg.x, o1b);
                EX2F(e, fmaf(q1, kg.y, a1)); s1a += e; o1a = fmaf(e, vg.y, o1a);
            }
        }
    } else {
        #pragma unroll
        for (int jy = 0; jy < KS; jy++) {
            const float2* kp = (const float2*)(ks_ + (r + jy)*SP + w0);
            const float2* vp = (const float2*)(vs_ + (r + jy)*SP + w0);
            float2 ka = kp[0], kc = kp[1], ke = kp[2], kg = kp[3];
            float2 va = vp[0], vc = vp[1], ve = vp[2], vg = vp[3];
            if (jy < 2) {
                // out0 taps jx: (ka.x,ka.y)=0,1  (kc.x,kc.y)=2,3  (ke.x,ke.y)=4,5  scalar kg.x=6
                ull A00 = pk(q0*relv[0], q0*relv[1]);
                ull A01 = pk(q0*relv[2], q0*relv[3]);
                ull A02 = pk(q0*relv[4], q0*relv[5]);
                // out1 taps jx: (ka.y,kc.x)=0,1  (kc.y,ke.x)=2,3  (ke.y,kg.x)=4,5  scalar kg.y=6
                ull A10 = pk(q1*relv[0], q1*relv[1]);
                ull A11 = pk(q1*relv[2], q1*relv[3]);
                ull A12 = pk(q1*relv[4], q1*relv[5]);
                tap2_poly(q02, pk(ka.x,ka.y), A00, va.x, va.y, s0a,o0a,s0b,o0b);
                tap2_poly(q02, pk(kc.x,kc.y), A01, vc.x, vc.y, s0a,o0a,s0b,o0b);
                tap2_poly(q02, pk(ke.x,ke.y), A02, ve.x, ve.y, s0a,o0a,s0b,o0b);
                tap2_poly(q12, pk(ka.y,kc.x), A10, va.y, vc.x, s1a,o1a,s1b,o1b);
                tap2_poly(q12, pk(kc.y,ke.x), A11, vc.y, ve.x, s1a,o1a,s1b,o1b);
                tap2_poly(q12, pk(ke.y,kg.x), A12, ve.y, vg.x, s1a,o1a,s1b,o1b);
                float e;
                EX2F(e, fmaf(q0, kg.x, q0*relv[6])); s0a += e; o0a = fmaf(e, vg.x, o0a);
                EX2F(e, fmaf(q1, kg.y, q1*relv[6])); s1a += e; o1a = fmaf(e, vg.y, o1a);
            } else {
                float e;
                EX2F(e, fmaf(q0, ka.x, q0*relv[0])); s0a += e; o0a = fmaf(e, va.x, o0a);
                EX2F(e, fmaf(q0, ka.y, q0*relv[1])); s0b += e; o0b = fmaf(e, va.y, o0b);
                EX2F(e, fmaf(q0, kc.x, q0*relv[2])); s0a += e; o0a = fmaf(e, vc.x, o0a);
                EX2F(e, fmaf(q0, kc.y, q0*relv[3])); s0b += e; o0b = fmaf(e, vc.y, o0b);
                EX2F(e, fmaf(q0, ke.x, q0*relv[4])); s0a += e; o0a = fmaf(e, ve.x, o0a);
                EX2F(e, fmaf(q0, ke.y, q0*relv[5])); s0b += e; o0b = fmaf(e, ve.y, o0b);
                EX2F(e, fmaf(q0, kg.x, q0*relv[6])); s0a += e; o0a = fmaf(e, vg.x, o0a);
                EX2F(e, fmaf(q1, ka.y, q1*relv[0])); s1a += e; o1a = fmaf(e, va.y, o1a);
                EX2F(e, fmaf(q1, kc.x, q1*relv[1])); s1b += e; o1b = fmaf(e, vc.x, o1b);
                EX2F(e, fmaf(q1, kc.y, q1*relv[2])); s1a += e; o1a = fmaf(e, vc.y, o1a);
                EX2F(e, fmaf(q1, ke.x, q1*relv[3])); s1b += e; o1b = fmaf(e, ve.x, o1b);
                EX2F(e, fmaf(q1, ke.y, q1*relv[4])); s1a += e; o1a = fmaf(e, ve.y, o1a);
                EX2F(e, fmaf(q1, kg.x, q1*relv[5])); s1b += e; o1b = fmaf(e, vg.x, o1b);
                EX2F(e, fmaf(q1, kg.y, q1*relv[6])); s1a += e; o1a = fmaf(e, vg.y, o1a);
            }
        }
    }

    float2 res;
    res.x = __fdividef(o0a + o0b, s0a + s0b);
    res.y = __fdividef(o1a + o1b, s1a + s1b);
    *(float2*)&out[(cbase + h)*W + w0] = res;
}

extern "C" void kernel_launch(void* const* d_in, const int* in_sizes, int n_in,
                              void* d_out, int out_size) {
    const float* x     = (const float*)d_in[0];
    const float* wq    = (const float*)d_in[1];
    const float* wk    = (const float*)d_in[2];
    const float* bk    = (const float*)d_in[3];
    const float* wv    = (const float*)d_in[4];
    const float* bv    = (const float*)d_in[5];
    const float* rel_x = (const float*)d_in[6];
    const float* rel_y = (const float*)d_in[7];
    float* out = (float*)d_out;

    qkv_kernel<<<392, 256>>>(x, wq, wk, bk, wv, bv);

    dim3 grid(H/TH, COUT, B);   // 1792 blocks
    attn_kernel<<<grid, 224>>>(rel_x, rel_y, bk, bv, out);
}